// round 6
// baseline (speedup 1.0000x reference)
#include <cuda_runtime.h>

#define BB 256
#define AA 128
#define DD 5
#define FATOM 256
#define FBOND 64
#define FTOT 320   // FATOM + FBOND
#define CC 256
#define CH 128                // columns per C-half
#define NROWS (BB * AA)
#define TILE_M 16
#define CF 32                 // f-rows per W chunk
#define NCHUNK (FTOT / CF)    // 10

typedef unsigned long long ull;

// Scratch (no device allocation allowed anywhere).
__device__ int g_count[DD];
__device__ int g_rows[DD * NROWS];

// ---------------- packed f32x2 helpers ----------------
__device__ __forceinline__ ull fma2(ull a, ull b, ull c) {
    ull d;
    asm("fma.rn.f32x2 %0, %1, %2, %3;" : "=l"(d) : "l"(a), "l"(b), "l"(c));
    return d;
}
__device__ __forceinline__ void unpack2(ull v, float& lo, float& hi) {
    asm("mov.b64 {%0, %1}, %2;" : "=f"(lo), "=f"(hi) : "l"(v));
}
__device__ __forceinline__ ull pack2(float lo, float hi) {
    ull r;
    asm("mov.b64 %0, {%1, %2};" : "=l"(r) : "f"(lo), "f"(hi));
    return r;
}
__device__ __forceinline__ void lds_v2u64(ull& a, ull& b, unsigned saddr) {
    asm volatile("ld.shared.v2.u64 {%0, %1}, [%2];"
                 : "=l"(a), "=l"(b) : "r"(saddr));
}

// ---------------- cp.async helpers ----------------
__device__ __forceinline__ void cp_async16(void* smem_dst, const void* gmem_src) {
    unsigned sa = (unsigned)__cvta_generic_to_shared(smem_dst);
    asm volatile("cp.async.cg.shared.global [%0], [%1], 16;\n"
                 :: "r"(sa), "l"(gmem_src) : "memory");
}
__device__ __forceinline__ void cp_commit() {
    asm volatile("cp.async.commit_group;\n" ::: "memory");
}
__device__ __forceinline__ void cp_wait1() {
    asm volatile("cp.async.wait_group 1;\n" ::: "memory");
}

// Kernel A (fused): per-row degree; deg==5 rows -> zero output row;
// deg<5 rows -> append to deg-list. Warp handles 4 rows via ballot.
// Append order varies but each row handled exactly once -> deterministic.
__global__ void __launch_bounds__(256) classify_zero_kernel(
    const int* __restrict__ edges, float4* __restrict__ out4)
{
    const int wid  = threadIdx.x >> 5;
    const int lane = threadIdx.x & 31;
    const int rbase = blockIdx.x * 32 + wid * 4;
    const float4 z = make_float4(0.f, 0.f, 0.f, 0.f);

#pragma unroll
    for (int i = 0; i < 4; i++) {
        const int row = rbase + i;
        int e = -1;
        if (lane < DD) e = edges[row * DD + lane];
        unsigned m = __ballot_sync(0xffffffffu, (lane < DD) && (e >= 0));
        int deg = __popc(m);
        if (deg == DD) {
            float4* o = out4 + row * (CC / 4);
            o[lane] = z;
            o[lane + 32] = z;
        } else if (lane == 0) {
            int pos = atomicAdd(&g_count[deg], 1);
            g_rows[deg * NROWS + pos] = row;
        }
    }
}

// Kernel B: per-deg grouped GEMM, C split in 2 halves per block.
// Tile = 16 rows x 128 cols. 256 threads: warp w = rows {2w, 2w+1},
// lane cq = cols 4cq..4cq+3 within the half. feat stored DUPLICATED
// ((v,v) u64 pairs) so fma.rn.f32x2 operands come straight from
// ld.shared.v2.u64 with zero packing movs. Only this block's C-half of W
// is staged (CF x 128 floats per chunk), double-buffered via cp.async.
__global__ void __launch_bounds__(256) gemm_kernel(
    const float4* __restrict__ atoms4, const float4* __restrict__ bonds4,
    const int* __restrict__ edges, const float* __restrict__ W,
    const float* __restrict__ bias, float* __restrict__ out)
{
    __shared__ ull   featd[TILE_M][FTOT];   // duplicated feat: 40 KB
    __shared__ float Wbuf[2][CF * CH];      // 2 x 16 KB

    const int deg = blockIdx.z;
    const int count = g_count[deg];
    if (count == 0) return;

    const int chalf = blockIdx.x;           // cols [chalf*128, +128)
    const int tid  = threadIdx.x;
    const int wid  = tid >> 5;
    const int lane = tid & 31;
    const int cq   = lane;                  // col quad within half
    const int c0   = chalf * CH + 4 * cq;   // first of this thread's 4 cols
    const float* Wh = W + deg * FTOT * CC + chalf * CH;  // this half's W base

    const float4 bq = *reinterpret_cast<const float4*>(&bias[deg * CC + c0]);
    const ull bvA = pack2(bq.x, bq.y);
    const ull bvB = pack2(bq.z, bq.w);

    // smem byte addresses for asm loads
    const unsigned wbase  = (unsigned)__cvta_generic_to_shared(&Wbuf[0][0]) + cq * 16;
    const unsigned f0base = (unsigned)__cvta_generic_to_shared(&featd[2 * wid][0]);
    const unsigned f1base = (unsigned)__cvta_generic_to_shared(&featd[2 * wid + 1][0]);

    // per-thread staging source: thread handles float4 index tid + 256*i of a
    // chunk; chunk layout = CF rows x 32 float4 (row-major, contiguous halves)
    const int sf  = tid >> 5;        // f-row group start (tid/32): rows sf, sf+8, ...
    const int sc4 = tid & 31;        // float4 within row

    for (int tile = blockIdx.y; tile * TILE_M < count; tile += gridDim.y) {
        const int base  = tile * TILE_M;
        const int nrows = min(TILE_M, count - base);

        __syncthreads();  // prior-iteration smem readers done

        // ---- Prefetch W chunks 0 and 1 (this half only) ----
#pragma unroll
        for (int c = 0; c < 2; c++) {
#pragma unroll
            for (int i = 0; i < 4; i++) {    // 4 float4 per thread
                const int f = sf + 8 * i;    // f-row within chunk
                cp_async16(&Wbuf[c][f * CH + sc4 * 4],
                           Wh + (c * CF + f) * CC + sc4 * 4);
            }
            cp_commit();
        }

        // ---- Feat build (duplicated): warp wid builds rows wid, wid+8 ----
#pragma unroll
        for (int rr = 0; rr < 2; rr++) {
            const int r = wid + rr * 8;
            if (r < nrows) {
                const int row   = g_rows[deg * NROWS + base + r];
                const int bbase = (row >> 7) << 7;  // b * AA
                int e[DD];
#pragma unroll
                for (int d = 0; d < DD; d++) e[d] = edges[row * DD + d];
#pragma unroll
                for (int k = 0; k < 2; k++) {
                    const int f4 = lane + 32 * k;      // float4 idx (f = 4*f4)
                    float4 v = atoms4[row * 64 + f4];
#pragma unroll
                    for (int d = 0; d < DD; d++) {
                        if (e[d] >= 0) {
                            float4 nv = atoms4[(bbase + e[d]) * 64 + f4];
                            v.x += nv.x; v.y += nv.y; v.z += nv.z; v.w += nv.w;
                        }
                    }
                    float4* dst = reinterpret_cast<float4*>(&featd[r][4 * f4]);
                    dst[0] = make_float4(v.x, v.x, v.y, v.y);
                    dst[1] = make_float4(v.z, v.z, v.w, v.w);
                }
                if (lane < 16) {
                    float4 s = make_float4(0.f, 0.f, 0.f, 0.f);
#pragma unroll
                    for (int d = 0; d < DD; d++) {
                        float4 bvv = bonds4[(row * DD + d) * 16 + lane];
                        s.x += bvv.x; s.y += bvv.y; s.z += bvv.z; s.w += bvv.w;
                    }
                    float4* dst = reinterpret_cast<float4*>(&featd[r][FATOM + 4 * lane]);
                    dst[0] = make_float4(s.x, s.x, s.y, s.y);
                    dst[1] = make_float4(s.z, s.z, s.w, s.w);
                }
            }
        }

        // ---- Main pipeline over W chunks ----
        ull acc00 = bvA, acc01 = bvB;   // row 2*wid
        ull acc10 = bvA, acc11 = bvB;   // row 2*wid+1

        for (int c = 0; c < NCHUNK; c++) {
            cp_wait1();          // chunk c landed (<=1 group outstanding)
            __syncthreads();     // chunk + feat (c==0) visible to all

            const unsigned ws = wbase + (c & 1) * (CF * CH * 4);
            const int fb = c * CF;
#pragma unroll
            for (int f4 = 0; f4 < CF; f4 += 4) {
                const unsigned fo = (fb + f4) * 8;   // byte offset into featd row
                ull p0, p1, p2, p3, q0, q1, q2, q3;
                lds_v2u64(p0, p1, f0base + fo);
                lds_v2u64(p2, p3, f0base + fo + 16);
                lds_v2u64(q0, q1, f1base + fo);
                lds_v2u64(q2, q3, f1base + fo + 16);
                ull wA, wB;
                lds_v2u64(wA, wB, ws + (f4 + 0) * (CH * 4));
                acc00 = fma2(p0, wA, acc00); acc01 = fma2(p0, wB, acc01);
                acc10 = fma2(q0, wA, acc10); acc11 = fma2(q0, wB, acc11);
                lds_v2u64(wA, wB, ws + (f4 + 1) * (CH * 4));
                acc00 = fma2(p1, wA, acc00); acc01 = fma2(p1, wB, acc01);
                acc10 = fma2(q1, wA, acc10); acc11 = fma2(q1, wB, acc11);
                lds_v2u64(wA, wB, ws + (f4 + 2) * (CH * 4));
                acc00 = fma2(p2, wA, acc00); acc01 = fma2(p2, wB, acc01);
                acc10 = fma2(q2, wA, acc10); acc11 = fma2(q2, wB, acc11);
                lds_v2u64(wA, wB, ws + (f4 + 3) * (CH * 4));
                acc00 = fma2(p3, wA, acc00); acc01 = fma2(p3, wB, acc01);
                acc10 = fma2(q3, wA, acc10); acc11 = fma2(q3, wB, acc11);
            }
            __syncthreads();     // everyone done reading Wbuf[c&1]
            if (c + 2 < NCHUNK) {
#pragma unroll
                for (int i = 0; i < 4; i++) {
                    const int f = sf + 8 * i;
                    cp_async16(&Wbuf[c & 1][f * CH + sc4 * 4],
                               Wh + ((c + 2) * CF + f) * CC + sc4 * 4);
                }
            }
            cp_commit();         // keep group count in step (may be empty)
        }

        // ---- Epilogue: relu + store float4 per row ----
#pragma unroll
        for (int rr = 0; rr < 2; rr++) {
            const int ri = 2 * wid + rr;
            if (ri < nrows) {
                const int row = g_rows[deg * NROWS + base + ri];
                float a, b2, cx, dx;
                unpack2(rr ? acc10 : acc00, a, b2);
                unpack2(rr ? acc11 : acc01, cx, dx);
                float4 o = make_float4(fmaxf(a, 0.f), fmaxf(b2, 0.f),
                                       fmaxf(cx, 0.f), fmaxf(dx, 0.f));
                *reinterpret_cast<float4*>(&out[row * CC + c0]) = o;
            }
        }
    }
}

extern "C" void kernel_launch(void* const* d_in, const int* in_sizes, int n_in,
                              void* d_out, int out_size) {
    const float* atoms = (const float*)d_in[0];   // (B, A, FA) f32
    const float* bonds = (const float*)d_in[1];   // (B, A, D, FB) f32
    const int*   edges = (const int*)d_in[2];     // (B, A, D) i32
    const float* W     = (const float*)d_in[3];   // (D, FA+FB, C) f32
    const float* bias  = (const float*)d_in[4];   // (D, C) f32
    float* out = (float*)d_out;                   // (B, A, C) f32

    // Reset compaction counters (memset node; no allocation).
    void* cnt_addr = nullptr;
    cudaGetSymbolAddress(&cnt_addr, g_count);
    cudaMemsetAsync(cnt_addr, 0, DD * sizeof(int));

    classify_zero_kernel<<<NROWS / 32, 256>>>(edges, (float4*)out);
    // grid: x = C-half, y = tile slots (stride loop), z = deg
    gemm_kernel<<<dim3(2, 80, DD), 256>>>((const float4*)atoms,
                                          (const float4*)bonds,
                                          edges, W, bias, out);
}